// round 12
// baseline (speedup 1.0000x reference)
#include <cuda_runtime.h>
#include <cuda_fp16.h>
#include <cstdint>

// ---------------- Problem constants ----------------
#define IN_F   512
#define OUT_F  512
#define NEXP   8
#define NGRP   32
#define TPG    2048
#define NTOK   (NGRP * TPG)
#define CHUNK  64

// ---------------- Scratch (no cudaMalloc allowed) ----------------
__device__ __align__(16) __half g_w[(size_t)NGRP * OUT_F * IN_F];    // 16.7 MB mixed weights fp16
__device__ __align__(16) __half g_xh[(size_t)NTOK * IN_F];           // 67 MB x in fp16
__device__ float g_bias_mix[NGRP * OUT_F];

// ---------------- helpers ----------------
static __device__ __forceinline__ uint32_t smem_u32(const void* p) {
    uint32_t a;
    asm("{ .reg .u64 t; cvta.to.shared.u64 t, %1; cvt.u32.u64 %0, t; }"
        : "=r"(a) : "l"(p));
    return a;
}

static __device__ __forceinline__ void cp_async16_cg(uint32_t dst, const void* src) {
    asm volatile("cp.async.cg.shared.global [%0], [%1], 16;"
                 :: "r"(dst), "l"(src) : "memory");
}
static __device__ __forceinline__ void cp_async_commit() {
    asm volatile("cp.async.commit_group;" ::: "memory");
}
static __device__ __forceinline__ void cp_async_wait0() {
    asm volatile("cp.async.wait_group 0;" ::: "memory");
}

static __device__ __forceinline__ void ldm_x4(uint32_t* r, uint32_t addr) {
    asm volatile("ldmatrix.sync.aligned.m8n8.x4.shared.b16 {%0,%1,%2,%3}, [%4];"
                 : "=r"(r[0]), "=r"(r[1]), "=r"(r[2]), "=r"(r[3]) : "r"(addr));
}

static __device__ __forceinline__ void mma_16816(float* c, const uint32_t* a, const uint32_t* b) {
    asm volatile(
        "mma.sync.aligned.m16n8k16.row.col.f32.f16.f16.f32 "
        "{%0,%1,%2,%3}, {%4,%5,%6,%7}, {%8,%9}, {%0,%1,%2,%3};"
        : "+f"(c[0]), "+f"(c[1]), "+f"(c[2]), "+f"(c[3])
        : "r"(a[0]), "r"(a[1]), "r"(a[2]), "r"(a[3]), "r"(b[0]), "r"(b[1]));
}

// ---------------- Kernel 0: convert x -> fp16 ----------------
__global__ void convert_x_kernel(const float* __restrict__ x)
{
    const size_t i = (size_t)blockIdx.x * 256 + threadIdx.x;   // 8-float unit
    const float4* src = reinterpret_cast<const float4*>(x) + i * 2;
    float4 a = src[0], b = src[1];
    __half2 h0 = __floats2half2_rn(a.x, a.y);
    __half2 h1 = __floats2half2_rn(a.z, a.w);
    __half2 h2 = __floats2half2_rn(b.x, b.y);
    __half2 h3 = __floats2half2_rn(b.z, b.w);
    reinterpret_cast<uint4*>(g_xh)[i] =
        make_uint4(*reinterpret_cast<uint32_t*>(&h0), *reinterpret_cast<uint32_t*>(&h1),
                   *reinterpret_cast<uint32_t*>(&h2), *reinterpret_cast<uint32_t*>(&h3));
}

// ---------------- Kernel 1: mix expert weights -> fp16 ----------------
// grid (256, 4): blockIdx.y owns 8 groups -> 4x parallelism vs one serial pass.
__global__ void mix_weights_kernel(const float* __restrict__ coeff,
                                   const float* __restrict__ we,
                                   const float* __restrict__ ws)
{
    __shared__ float c_sm[NGRP * NEXP];
    int t = threadIdx.x;
    c_sm[t] = coeff[t];
    __syncthreads();

    int p = blockIdx.x * 256 + t;            // float4 index 0..65535
    const float4* ws4 = reinterpret_cast<const float4*>(ws);
    const float4* we4 = reinterpret_cast<const float4*>(we);
    float4 s = ws4[p];
    float4 e4[NEXP];
#pragma unroll
    for (int e = 0; e < NEXP; e++) e4[e] = we4[e * 65536 + p];

    const int g0 = blockIdx.y * 8;
#pragma unroll
    for (int gi = 0; gi < 8; gi++) {
        const int g = g0 + gi;
        const float* cg = c_sm + g * NEXP;
        float4 acc = s;
#pragma unroll
        for (int e = 0; e < NEXP; e++) {
            acc.x = fmaf(cg[e], e4[e].x, acc.x);
            acc.y = fmaf(cg[e], e4[e].y, acc.y);
            acc.z = fmaf(cg[e], e4[e].z, acc.z);
            acc.w = fmaf(cg[e], e4[e].w, acc.w);
        }
        __half2 p01 = __floats2half2_rn(acc.x, acc.y);
        __half2 p23 = __floats2half2_rn(acc.z, acc.w);
        uint2 packed = make_uint2(*reinterpret_cast<uint32_t*>(&p01),
                                  *reinterpret_cast<uint32_t*>(&p23));
        reinterpret_cast<uint2*>(g_w)[(size_t)g * 65536 + p] = packed;
    }
}

// ---------------- Kernel 2: mix bias ----------------
__global__ void mix_bias_kernel(const float* __restrict__ coeff,
                                const float* __restrict__ be,
                                const float* __restrict__ bs)
{
    int g = blockIdx.x;
    int n = threadIdx.x;
    float acc = bs[n];
#pragma unroll
    for (int e = 0; e < NEXP; e++)
        acc = fmaf(coeff[g * NEXP + e], be[e * OUT_F + n], acc);
    g_bias_mix[g * OUT_F + n] = acc;
}

// ---------------- Kernel 3: grouped GEMM, big warp tiles ----------------
// CTA 128x256, 256 threads, 8 warps (2m x 4n), warp tile 64x64 (acc 128 regs).
// K = 8 chunks of 64, double-buffered cp.async, one __syncthreads per chunk.
// 144B SMEM row stride -> conflict-free ldmatrix phases.
// LDSM traffic: 4 B/output (vs 6 B/output with 32x64 warp tiles).
#define ROWB    144
#define ATILE   (128 * ROWB)            // 18432 B
#define WTILE   (256 * ROWB)            // 36864 B
#define AOFF(b)   ((b) * (ATILE + WTILE))
#define WOFF(b)   (AOFF(b) + ATILE)
#define SMEM_TOTAL (2 * (ATILE + WTILE))  // 110592 B -> 1 CTA/SM

__global__ void __launch_bounds__(256, 1)
moe_gemm_kernel(float* __restrict__ out)
{
    extern __shared__ __align__(128) uint8_t smem[];
    const uint32_t sb = smem_u32(smem);

    const int tid  = threadIdx.x;
    const int lane = tid & 31;
    const int wid  = tid >> 5;
    const int wm   = (wid & 1) * 64;    // warp m offset (0, 64)
    const int wn   = (wid >> 1) * 64;   // warp n offset (0, 64, 128, 192)

    const int bx = blockIdx.x;           // 0..1023
    const int g  = bx >> 5;              // 32 tiles per group
    const int mt = (bx >> 1) & 15;
    const int nt = bx & 1;
    const int m0 = g * TPG + mt * 128;
    const int n0 = nt * 256;

    const __half* wg = g_w  + (size_t)g * OUT_F * IN_F + (size_t)n0 * IN_F;
    const __half* ag = g_xh + (size_t)m0 * IN_F;

    auto cpA = [&](int kc, int b) {
#pragma unroll
        for (int u = 0; u < 4; u++) {
            const int lin = tid + u * 256;      // 0..1023
            const int row = lin >> 3;
            const int seg = lin & 7;
            cp_async16_cg(sb + AOFF(b) + row * ROWB + seg * 16,
                          ag + (size_t)row * IN_F + kc * CHUNK + seg * 8);
        }
    };
    auto cpW = [&](int kc, int b) {
#pragma unroll
        for (int u = 0; u < 8; u++) {
            const int lin = tid + u * 256;      // 0..2047
            const int row = lin >> 3;           // 0..255
            const int seg = lin & 7;
            cp_async16_cg(sb + WOFF(b) + row * ROWB + seg * 16,
                          wg + (size_t)row * IN_F + kc * CHUNK + seg * 8);
        }
    };

    float acc[4][8][4];
#pragma unroll
    for (int i = 0; i < 4; i++)
#pragma unroll
        for (int j = 0; j < 8; j++)
#pragma unroll
            for (int kk = 0; kk < 4; kk++) acc[i][j][kk] = 0.0f;

    // ---- prologue: fill buffer 0 ----
    cpA(0, 0);
    cpW(0, 0);
    cp_async_commit();
    cp_async_wait0();
    __syncthreads();

    // ---- mainloop: 8 chunks, ONE barrier per chunk ----
    for (int kc = 0; kc < 8; kc++) {
        const int b = kc & 1;

        if (kc + 1 < 8) {
            cpA(kc + 1, b ^ 1);
            cpW(kc + 1, b ^ 1);
            cp_async_commit();
        }

        const uint32_t a_b = sb + AOFF(b);
        const uint32_t w_b = sb + WOFF(b);

#pragma unroll
        for (int s = 0; s < 4; s++) {
            // B fragments: 4x ldmatrix.x4 over 64 n (two n8 tiles each)
            uint32_t bfr[16];
#pragma unroll
            for (int p = 0; p < 4; p++) {
                const uint32_t baddr = w_b
                    + (uint32_t)(wn + p * 16 + (lane >> 4) * 8 + (lane & 7)) * ROWB
                    + s * 32 + ((lane >> 3) & 1) * 16;
                ldm_x4(bfr + p * 4, baddr);
            }
            // A fragments: 4 m16 tiles over 64 m
            uint32_t afr[4][4];
#pragma unroll
            for (int m = 0; m < 4; m++) {
                const uint32_t aaddr = a_b
                    + (uint32_t)(wm + m * 16 + (lane & 15)) * ROWB
                    + s * 32 + (lane >> 4) * 16;
                ldm_x4(afr[m], aaddr);
            }
#pragma unroll
            for (int m = 0; m < 4; m++) {
#pragma unroll
                for (int n = 0; n < 8; n++) {
                    const uint32_t* bp = bfr + (n >> 1) * 4 + (n & 1) * 2;
                    mma_16816(acc[m][n], afr[m], bp);
                }
            }
        }

        if (kc + 1 < 8) cp_async_wait0();
        __syncthreads();
    }

    // ---- epilogue: bias add + direct float2 stores ----
    const float* bias = g_bias_mix + g * OUT_F + n0;
    const int crow = lane >> 2;
    const int ccol2 = 2 * (lane & 3);
#pragma unroll
    for (int m = 0; m < 4; m++) {
        const int row = m0 + wm + m * 16 + crow;
#pragma unroll
        for (int n = 0; n < 8; n++) {
            const int col = wn + n * 8 + ccol2;
            const float2 bv = *reinterpret_cast<const float2*>(bias + col);
            float2 o0 = make_float2(acc[m][n][0] + bv.x, acc[m][n][1] + bv.y);
            float2 o1 = make_float2(acc[m][n][2] + bv.x, acc[m][n][3] + bv.y);
            *reinterpret_cast<float2*>(out + (size_t)row * OUT_F + n0 + col) = o0;
            *reinterpret_cast<float2*>(out + (size_t)(row + 8) * OUT_F + n0 + col) = o1;
        }
    }
}

// ---------------- Launch ----------------
extern "C" void kernel_launch(void* const* d_in, const int* in_sizes, int n_in,
                              void* d_out, int out_size)
{
    const float* x     = (const float*)d_in[0];
    const float* coeff = (const float*)d_in[1];
    const float* we    = (const float*)d_in[2];
    const float* be    = (const float*)d_in[3];
    const float* ws    = (const float*)d_in[4];
    const float* bs    = (const float*)d_in[5];
    float* out = (float*)d_out;

    cudaFuncSetAttribute(moe_gemm_kernel,
                         cudaFuncAttributeMaxDynamicSharedMemorySize, SMEM_TOTAL);

    convert_x_kernel<<<NTOK * IN_F / (256 * 8), 256>>>(x);
    mix_weights_kernel<<<dim3(256, 4), 256>>>(coeff, we, ws);
    mix_bias_kernel<<<NGRP, OUT_F>>>(coeff, be, bs);
    moe_gemm_kernel<<<NGRP * 16 * 2, 256, SMEM_TOTAL>>>(out);
}

// round 13
// speedup vs baseline: 1.2005x; 1.2005x over previous
#include <cuda_runtime.h>
#include <cuda_fp16.h>
#include <cstdint>

// ---------------- Problem constants ----------------
#define IN_F   512
#define OUT_F  512
#define NEXP   8
#define NGRP   32
#define TPG    2048
#define NTOK   (NGRP * TPG)
#define CHUNK  64

// ---------------- Scratch (no cudaMalloc allowed) ----------------
__device__ __align__(16) __half g_w[(size_t)NGRP * OUT_F * IN_F];    // 16.7 MB mixed weights fp16
__device__ __align__(16) __half g_xh[(size_t)NTOK * IN_F];           // 67 MB x in fp16
__device__ float g_bias_mix[NGRP * OUT_F];

// ---------------- helpers ----------------
static __device__ __forceinline__ uint32_t smem_u32(const void* p) {
    uint32_t a;
    asm("{ .reg .u64 t; cvta.to.shared.u64 t, %1; cvt.u32.u64 %0, t; }"
        : "=r"(a) : "l"(p));
    return a;
}

static __device__ __forceinline__ void cp_async16_cg(uint32_t dst, const void* src) {
    asm volatile("cp.async.cg.shared.global [%0], [%1], 16;"
                 :: "r"(dst), "l"(src) : "memory");
}
static __device__ __forceinline__ void cp_async_commit() {
    asm volatile("cp.async.commit_group;" ::: "memory");
}

static __device__ __forceinline__ void ldm_x4(uint32_t* r, uint32_t addr) {
    asm volatile("ldmatrix.sync.aligned.m8n8.x4.shared.b16 {%0,%1,%2,%3}, [%4];"
                 : "=r"(r[0]), "=r"(r[1]), "=r"(r[2]), "=r"(r[3]) : "r"(addr));
}

static __device__ __forceinline__ void mma_16816(float* c, const uint32_t* a, const uint32_t* b) {
    asm volatile(
        "mma.sync.aligned.m16n8k16.row.col.f32.f16.f16.f32 "
        "{%0,%1,%2,%3}, {%4,%5,%6,%7}, {%8,%9}, {%0,%1,%2,%3};"
        : "+f"(c[0]), "+f"(c[1]), "+f"(c[2]), "+f"(c[3])
        : "r"(a[0]), "r"(a[1]), "r"(a[2]), "r"(a[3]), "r"(b[0]), "r"(b[1]));
}

// ---------------- Kernel 0: convert x -> fp16 ----------------
__global__ void convert_x_kernel(const float* __restrict__ x)
{
    const size_t i = (size_t)blockIdx.x * 256 + threadIdx.x;   // 8-float unit
    const float4* src = reinterpret_cast<const float4*>(x) + i * 2;
    float4 a = src[0], b = src[1];
    __half2 h0 = __floats2half2_rn(a.x, a.y);
    __half2 h1 = __floats2half2_rn(a.z, a.w);
    __half2 h2 = __floats2half2_rn(b.x, b.y);
    __half2 h3 = __floats2half2_rn(b.z, b.w);
    reinterpret_cast<uint4*>(g_xh)[i] =
        make_uint4(*reinterpret_cast<uint32_t*>(&h0), *reinterpret_cast<uint32_t*>(&h1),
                   *reinterpret_cast<uint32_t*>(&h2), *reinterpret_cast<uint32_t*>(&h3));
}

// ---------------- Kernel 1: mix expert weights -> fp16 ----------------
// grid (256, 4): blockIdx.y owns 8 groups.
__global__ void mix_weights_kernel(const float* __restrict__ coeff,
                                   const float* __restrict__ we,
                                   const float* __restrict__ ws)
{
    __shared__ float c_sm[NGRP * NEXP];
    int t = threadIdx.x;
    c_sm[t] = coeff[t];
    __syncthreads();

    int p = blockIdx.x * 256 + t;            // float4 index 0..65535
    const float4* ws4 = reinterpret_cast<const float4*>(ws);
    const float4* we4 = reinterpret_cast<const float4*>(we);
    float4 s = ws4[p];
    float4 e4[NEXP];
#pragma unroll
    for (int e = 0; e < NEXP; e++) e4[e] = we4[e * 65536 + p];

    const int g0 = blockIdx.y * 8;
#pragma unroll
    for (int gi = 0; gi < 8; gi++) {
        const int g = g0 + gi;
        const float* cg = c_sm + g * NEXP;
        float4 acc = s;
#pragma unroll
        for (int e = 0; e < NEXP; e++) {
            acc.x = fmaf(cg[e], e4[e].x, acc.x);
            acc.y = fmaf(cg[e], e4[e].y, acc.y);
            acc.z = fmaf(cg[e], e4[e].z, acc.z);
            acc.w = fmaf(cg[e], e4[e].w, acc.w);
        }
        __half2 p01 = __floats2half2_rn(acc.x, acc.y);
        __half2 p23 = __floats2half2_rn(acc.z, acc.w);
        uint2 packed = make_uint2(*reinterpret_cast<uint32_t*>(&p01),
                                  *reinterpret_cast<uint32_t*>(&p23));
        reinterpret_cast<uint2*>(g_w)[(size_t)g * 65536 + p] = packed;
    }
}

// ---------------- Kernel 2: mix bias ----------------
__global__ void mix_bias_kernel(const float* __restrict__ coeff,
                                const float* __restrict__ be,
                                const float* __restrict__ bs)
{
    int g = blockIdx.x;
    int n = threadIdx.x;
    float acc = bs[n];
#pragma unroll
    for (int e = 0; e < NEXP; e++)
        acc = fmaf(coeff[g * NEXP + e], be[e * OUT_F + n], acc);
    g_bias_mix[g * OUT_F + n] = acc;
}

// ---------------- Kernel 3: grouped GEMM, 3-stage cp.async pipeline ----------------
// CTA 128x128, 8 warps (warp 32x64), occ=2. K = 8 chunks of 64.
// THREE SMEM stages; wait_group 1 -> each chunk's loads get ~2 compute spans
// of latency slack. One __syncthreads per chunk. 144B rows, conflict-free ldmatrix.
#define ROWB    144
#define TILE    (128 * ROWB)             // 18432 B
#define STAGEB  (2 * TILE)               // A + W per stage
#define AOFF(s)   ((s) * STAGEB)
#define WOFF(s)   (AOFF(s) + TILE)
#define SMEM_TOTAL (3 * STAGEB)          // 110592 B -> 2 CTAs/SM

__global__ void __launch_bounds__(256, 2)
moe_gemm_kernel(float* __restrict__ out)
{
    extern __shared__ __align__(128) uint8_t smem[];
    const uint32_t sb = smem_u32(smem);

    const int tid  = threadIdx.x;
    const int lane = tid & 31;
    const int wid  = tid >> 5;
    const int wm   = (wid & 3) * 32;   // warp m offset
    const int wn   = (wid >> 2) * 64;  // warp n offset

    const int bx = blockIdx.x;          // 0..2047
    const int g  = bx >> 6;
    const int mt = (bx >> 2) & 15;
    const int nt = bx & 3;
    const int m0 = g * TPG + mt * 128;
    const int n0 = nt * 128;

    const __half* wg = g_w  + (size_t)g * OUT_F * IN_F + (size_t)n0 * IN_F;
    const __half* ag = g_xh + (size_t)m0 * IN_F;

    auto cpStage = [&](int kc, int s) {
#pragma unroll
        for (int u = 0; u < 4; u++) {
            const int lin = tid + u * 256;      // 0..1023
            const int row = lin >> 3;
            const int seg = lin & 7;
            cp_async16_cg(sb + AOFF(s) + row * ROWB + seg * 16,
                          ag + (size_t)row * IN_F + kc * CHUNK + seg * 8);
        }
#pragma unroll
        for (int u = 0; u < 4; u++) {
            const int lin = tid + u * 256;
            const int row = lin >> 3;
            const int seg = lin & 7;
            cp_async16_cg(sb + WOFF(s) + row * ROWB + seg * 16,
                          wg + (size_t)row * IN_F + kc * CHUNK + seg * 8);
        }
        cp_async_commit();
    };

    float acc[2][8][4];
#pragma unroll
    for (int i = 0; i < 2; i++)
#pragma unroll
        for (int j = 0; j < 8; j++)
#pragma unroll
            for (int kk = 0; kk < 4; kk++) acc[i][j][kk] = 0.0f;

    // ---- prologue: stages 0 and 1 in flight ----
    cpStage(0, 0);
    cpStage(1, 1);

    // ---- mainloop: 8 chunks, one barrier per chunk ----
    for (int kc = 0; kc < 8; kc++) {
        const int s3 = kc % 3;

        // wait for stage kc; keep stage kc+1 in flight (tail: drain all)
        if (kc < 7) asm volatile("cp.async.wait_group 1;" ::: "memory");
        else        asm volatile("cp.async.wait_group 0;" ::: "memory");
        __syncthreads();   // also ensures prior readers of the stage we write next are done

        if (kc + 2 < 8) cpStage(kc + 2, (kc + 2) % 3);

        const uint32_t a_b = sb + AOFF(s3);
        const uint32_t w_b = sb + WOFF(s3);

#pragma unroll
        for (int s = 0; s < 4; s++) {
            uint32_t bfr[16];
#pragma unroll
            for (int p = 0; p < 4; p++) {
                const uint32_t baddr = w_b
                    + (uint32_t)(wn + p * 16 + (lane >> 4) * 8 + (lane & 7)) * ROWB
                    + s * 32 + ((lane >> 3) & 1) * 16;
                ldm_x4(bfr + p * 4, baddr);
            }
            uint32_t ah[2][4];
#pragma unroll
            for (int m = 0; m < 2; m++) {
                const uint32_t arow_l = (uint32_t)(wm + m * 16 + (lane & 15)) * ROWB
                                      + s * 32 + (lane >> 4) * 16;
                ldm_x4(ah[m], a_b + arow_l);
            }
#pragma unroll
            for (int m = 0; m < 2; m++) {
#pragma unroll
                for (int n = 0; n < 8; n++) {
                    const uint32_t* bp = bfr + (n >> 1) * 4 + (n & 1) * 2;
                    mma_16816(acc[m][n], ah[m], bp);
                }
            }
        }
    }

    // ---- epilogue: bias add + direct float2 stores ----
    const float* bias = g_bias_mix + g * OUT_F + n0;
    const int crow = lane >> 2;
    const int ccol2 = 2 * (lane & 3);
#pragma unroll
    for (int m = 0; m < 2; m++) {
        const int row = m0 + wm + m * 16 + crow;
#pragma unroll
        for (int n = 0; n < 8; n++) {
            const int col = wn + n * 8 + ccol2;
            const float2 bv = *reinterpret_cast<const float2*>(bias + col);
            float2 o0 = make_float2(acc[m][n][0] + bv.x, acc[m][n][1] + bv.y);
            float2 o1 = make_float2(acc[m][n][2] + bv.x, acc[m][n][3] + bv.y);
            *reinterpret_cast<float2*>(out + (size_t)row * OUT_F + n0 + col) = o0;
            *reinterpret_cast<float2*>(out + (size_t)(row + 8) * OUT_F + n0 + col) = o1;
        }
    }
}

// ---------------- Launch ----------------
extern "C" void kernel_launch(void* const* d_in, const int* in_sizes, int n_in,
                              void* d_out, int out_size)
{
    const float* x     = (const float*)d_in[0];
    const float* coeff = (const float*)d_in[1];
    const float* we    = (const float*)d_in[2];
    const float* be    = (const float*)d_in[3];
    const float* ws    = (const float*)d_in[4];
    const float* bs    = (const float*)d_in[5];
    float* out = (float*)d_out;

    cudaFuncSetAttribute(moe_gemm_kernel,
                         cudaFuncAttributeMaxDynamicSharedMemorySize, SMEM_TOTAL);

    convert_x_kernel<<<NTOK * IN_F / (256 * 8), 256>>>(x);
    mix_weights_kernel<<<dim3(256, 4), 256>>>(coeff, we, ws);
    mix_bias_kernel<<<NGRP, OUT_F>>>(coeff, be, bs);
    moe_gemm_kernel<<<NGRP * 16 * 4, 256, SMEM_TOTAL>>>(out);
}